// round 6
// baseline (speedup 1.0000x reference)
#include <cuda_runtime.h>
#include <math.h>
#include <stdint.h>

// ---------------- problem constants ----------------
constexpr int cB  = 2;
constexpr int cL  = 4096;
constexpr int cD  = 1024;   // D_MODEL
constexpr int cKD = 768;    // KEY_DIM
constexpr int cVD = 1536;   // VALUE_DIM
constexpr int cH  = 8;
constexpr int cDK = 96;     // per-head qk dim
constexpr int cDV = 192;    // per-head v dim
constexpr int cCS = 64;     // chunk size
constexpr int cNC = cL / cCS;       // 64 chunks per sequence
constexpr int cM  = cB * cL;        // 8192 tokens
constexpr int cBH = cB * cH;        // 16
constexpr int cNP = cKD + cKD + cVD + cVD;  // 4608 packed projection width

// ---------------- scratch (device globals; no cudaMalloc allowed) ----------------
__device__ uint32_t g_Wcat[cD * cNP];   // packed [Wq|Wk|Wv|Wg], tf32 bits
__device__ uint32_t g_WoT [cVD * cD];   // Wo, tf32 bits
__device__ uint32_t g_uT  [cM * cD];    // u, tf32 bits
__device__ float g_proj[cM * cNP];      // packed projection outputs (fp32)
__device__ float g_qn [cM * cKD];   // head layout; becomes qe after chunk_pre
__device__ float g_kn [cM * cKD];   // head layout; becomes kd after chunk_pre
__device__ float g_vh [cM * cVD];   // head layout; becomes u_ after chunk_pre
__device__ float g_kce[cM * cKD];   // kcd * exp(dec)
__device__ float g_gk [cBH * cL];
__device__ float g_bt [cBH * cL];
__device__ float g_at [cBH * cNC * cCS * cCS];  // intra-chunk attn
__device__ float g_edl[cBH * cNC];
__device__ float g_o  [cM * cVD];   // (b,h,l,dv)
__device__ uint32_t g_on [cM * cVD];   // gated+normed, tf32 bits

// ---------------- tf32 helpers ----------------
__device__ __forceinline__ uint32_t f2tf32(float f)
{
    uint32_t r;
    asm("cvt.rna.tf32.f32 %0, %1;" : "=r"(r) : "f"(f));
    return r;
}

__device__ __forceinline__ void mma_tf32(float c[4], const uint32_t a[4], const uint32_t b[2])
{
    asm volatile(
        "mma.sync.aligned.m16n8k8.row.col.f32.tf32.tf32.f32 "
        "{%0,%1,%2,%3}, {%4,%5,%6,%7}, {%8,%9}, {%0,%1,%2,%3};"
        : "+f"(c[0]), "+f"(c[1]), "+f"(c[2]), "+f"(c[3])
        : "r"(a[0]), "r"(a[1]), "r"(a[2]), "r"(a[3]), "r"(b[0]), "r"(b[1]));
}

#define CP16(dst, src) \
    asm volatile("cp.async.cg.shared.global [%0], [%1], 16;" :: "r"(dst), "l"(src))

// ---------------- tf32 tensor-core GEMM (5-stage cp.async pipeline) ----------------
// C[M,N] = A[M,K] @ B[K,N], A/B already tf32 bit-patterns, row-major.
// M%128==0, N%128==0, K%16==0, K/16 >= 5. Dynamic smem: 94720 bytes.
constexpr int GEMM_STAGES = 5;
constexpr int GEMM_SMEM = GEMM_STAGES * (128 * 20 + 16 * 136) * 4;
__global__ void __launch_bounds__(256, 2)
gemm_tf32_kernel(const uint32_t* __restrict__ A, int lda,
                 const uint32_t* __restrict__ B, int ldb,
                 float* __restrict__ C, int ldc,
                 int M, int N, int K)
{
    extern __shared__ uint32_t smem_u[];
    typedef uint32_t AsT[128][20];
    typedef uint32_t BsT[16][136];
    AsT* As = (AsT*)smem_u;
    BsT* Bs = (BsT*)(smem_u + GEMM_STAGES * 128 * 20);

    const int tid  = threadIdx.x;
    const int wid  = tid >> 5;
    const int lane = tid & 31;
    const int g    = lane >> 2;
    const int t    = lane & 3;
    const int wm   = (wid >> 2) * 64;   // warp m offset
    const int wn   = (wid & 3) * 32;    // warp n offset

    const int bm = blockIdx.y * 128;
    const int bn = blockIdx.x * 128;

    const int arow = tid >> 1;           // 0..127
    const int akb  = (tid & 1) * 8;      // 0 or 8
    const int bkr  = tid >> 4;           // 0..15
    const int bnb  = (tid & 15) * 8;     // 0..120

    const uint32_t* Ag = A + (size_t)(bm + arow) * lda + akb;
    const uint32_t* Bg = B + (size_t)bkr * ldb + bn + bnb;

    uint32_t sa[GEMM_STAGES], sb[GEMM_STAGES];
#pragma unroll
    for (int s = 0; s < GEMM_STAGES; s++) {
        sa[s] = (uint32_t)__cvta_generic_to_shared(&As[s][arow][akb]);
        sb[s] = (uint32_t)__cvta_generic_to_shared(&Bs[s][bkr][bnb]);
    }

    float acc[4][4][4];
#pragma unroll
    for (int i = 0; i < 4; i++)
#pragma unroll
        for (int j = 0; j < 4; j++)
#pragma unroll
            for (int r = 0; r < 4; r++) acc[i][j][r] = 0.f;

    const int nt = K >> 4;

    // prologue: stages 0..3
#pragma unroll
    for (int s = 0; s < GEMM_STAGES - 1; s++) {
        const uint32_t* a = Ag + (size_t)s * 16;
        const uint32_t* b = Bg + (size_t)s * 16 * ldb;
        CP16(sa[s], a); CP16(sa[s] + 16, a + 4);
        CP16(sb[s], b); CP16(sb[s] + 16, b + 4);
        asm volatile("cp.async.commit_group;");
    }

    int buf = 0, pre = GEMM_STAGES - 1;   // pre = stage index of (kt + STAGES-1)
    for (int kt = 0; kt < nt; kt++) {
        asm volatile("cp.async.wait_group %0;" :: "n"(GEMM_STAGES - 2));
        __syncthreads();

#pragma unroll
        for (int ks = 0; ks < 16; ks += 8) {
            uint32_t af[4][4], bf[4][2];
#pragma unroll
            for (int mi = 0; mi < 4; mi++) {
                int mr = wm + mi * 16;
                af[mi][0] = As[buf][mr + g][ks + t];
                af[mi][1] = As[buf][mr + g + 8][ks + t];
                af[mi][2] = As[buf][mr + g][ks + t + 4];
                af[mi][3] = As[buf][mr + g + 8][ks + t + 4];
            }
#pragma unroll
            for (int ni = 0; ni < 4; ni++) {
                int nc = wn + ni * 8;
                bf[ni][0] = Bs[buf][ks + t][nc + g];
                bf[ni][1] = Bs[buf][ks + t + 4][nc + g];
            }
#pragma unroll
            for (int mi = 0; mi < 4; mi++)
#pragma unroll
                for (int ni = 0; ni < 4; ni++)
                    mma_tf32(acc[mi][ni], af[mi], bf[ni]);
        }

        if (kt + GEMM_STAGES - 1 < nt) {
            const uint32_t* a = Ag + (size_t)(kt + GEMM_STAGES - 1) * 16;
            const uint32_t* b = Bg + (size_t)(kt + GEMM_STAGES - 1) * 16 * ldb;
            CP16(sa[pre], a); CP16(sa[pre] + 16, a + 4);
            CP16(sb[pre], b); CP16(sb[pre] + 16, b + 4);
        }
        asm volatile("cp.async.commit_group;");
        if (++buf == GEMM_STAGES) buf = 0;
        if (++pre == GEMM_STAGES) pre = 0;
    }

    // epilogue
#pragma unroll
    for (int mi = 0; mi < 4; mi++) {
#pragma unroll
        for (int ni = 0; ni < 4; ni++) {
            int row0 = bm + wm + mi * 16 + g;
            int col  = bn + wn + ni * 8 + 2 * t;
            *(float2*)(C + (size_t)row0 * ldc + col) = make_float2(acc[mi][ni][0], acc[mi][ni][1]);
            *(float2*)(C + (size_t)(row0 + 8) * ldc + col) = make_float2(acc[mi][ni][2], acc[mi][ni][3]);
        }
    }
}

// ---------------- pack [Wq|Wk|Wv|Wg] into one tf32 matrix ----------------
__global__ void pack_w_kernel(const float* __restrict__ Wq, const float* __restrict__ Wk,
                              const float* __restrict__ Wv, const float* __restrict__ Wg)
{
    int idx = blockIdx.x * blockDim.x + threadIdx.x;
    if (idx >= cD * cNP) return;
    int row = idx / cNP, col = idx % cNP;
    float v;
    if (col < cKD)            v = Wq[row * cKD + col];
    else if (col < 2 * cKD)   v = Wk[row * cKD + col - cKD];
    else if (col < 2 * cKD + cVD) v = Wv[row * cVD + col - 2 * cKD];
    else                      v = Wg[row * cVD + col - 2 * cKD - cVD];
    g_Wcat[idx] = f2tf32(v);
}

__global__ void pack_wo_kernel(const float* __restrict__ Wo)
{
    int idx = blockIdx.x * blockDim.x + threadIdx.x;
    if (idx >= cVD * cD) return;
    g_WoT[idx] = f2tf32(Wo[idx]);
}

__global__ void convert_u_kernel(const float4* __restrict__ u4)
{
    int idx = blockIdx.x * blockDim.x + threadIdx.x;
    if (idx >= cM * cD / 4) return;
    float4 v = u4[idx];
    uint4 r;
    r.x = f2tf32(v.x); r.y = f2tf32(v.y); r.z = f2tf32(v.z); r.w = f2tf32(v.w);
    ((uint4*)g_uT)[idx] = r;
}

// ---------------- gk / beta projections: warp per token, W in smem ----------------
__global__ void proj_gates_kernel(const float* __restrict__ u, const float* __restrict__ Wgk,
                                  const float* __restrict__ Wb, const float* __restrict__ b_b,
                                  const float* __restrict__ A_log, const float* __restrict__ dt_bias)
{
    extern __shared__ float sW[];   // [1024][16]
    const int tid = threadIdx.x;
    const int wid = tid >> 5;
    const int lane = tid & 31;

    for (int idx = tid; idx < cD * 16; idx += 256) {
        int i = idx >> 4, c = idx & 15;
        sW[idx] = (c < 8) ? Wgk[i * cH + c] : Wb[i * cH + (c - 8)];
    }
    __syncthreads();

    int m = blockIdx.x * 8 + wid;
    const float* ur = u + (size_t)m * cD;
    float s[16];
#pragma unroll
    for (int c = 0; c < 16; c++) s[c] = 0.f;
    for (int j = 0; j < 32; j++) {
        int i = lane + 32 * j;
        float uv = __ldg(ur + i);
        const float* wr = sW + i * 16;
#pragma unroll
        for (int c = 0; c < 16; c++) s[c] += uv * wr[c];
    }
#pragma unroll
    for (int c = 0; c < 16; c++) {
#pragma unroll
        for (int o = 16; o; o >>= 1) s[c] += __shfl_xor_sync(0xffffffffu, s[c], o);
    }
    if (lane < 8) {
        int h = lane;
        float x  = s[h] + dt_bias[h];
        float sp = (x > 20.f) ? x : log1pf(expf(x));
        float gkv = -expf(A_log[h]) * sp;
        int b = m / cL, l = m % cL;
        g_gk[((size_t)(b * cH + h)) * cL + l] = gkv;
    } else {
        int h = lane - 8;
        float bv = 1.f / (1.f + expf(-(s[8 + h] + b_b[h])));
        int b = m / cL, l = m % cL;
        g_bt[((size_t)(b * cH + h)) * cL + l] = bv;
    }
}

// ---------------- fused conv + SiLU + L2norm for q,k; writes head layout ----------------
__global__ void conv_qk_norm_kernel(const float* __restrict__ wq, const float* __restrict__ wk)
{
    int gw = (blockIdx.x * blockDim.x + threadIdx.x) >> 5;
    int lane = threadIdx.x & 31;
    if (gw >= cM * cH) return;
    int m = gw / cH, h = gw % cH;
    int b = m / cL, l = m % cL;
    const size_t rowbase = (size_t)(m - l) * cNP;

    float qv[3], kv[3];
    float ssq = 0.f, ssk = 0.f;
#pragma unroll
    for (int r = 0; r < 3; r++) {
        int c = h * cDK + lane + 32 * r;     // q column; k column = cKD + c
        float aq = 0.f, ak = 0.f;
#pragma unroll
        for (int j = 0; j < 4; j++) {
            int ll = l - 3 + j;
            if (ll >= 0) {
                const float* row = g_proj + rowbase + (size_t)ll * cNP;
                aq += row[c]       * wq[c * 4 + j];
                ak += row[cKD + c] * wk[c * 4 + j];
            }
        }
        aq = aq / (1.f + expf(-aq));
        ak = ak / (1.f + expf(-ak));
        qv[r] = aq; kv[r] = ak;
        ssq += aq * aq; ssk += ak * ak;
    }
#pragma unroll
    for (int o = 16; o; o >>= 1) {
        ssq += __shfl_xor_sync(0xffffffffu, ssq, o);
        ssk += __shfl_xor_sync(0xffffffffu, ssk, o);
    }
    float iq = 1.f / fmaxf(sqrtf(ssq), 1e-12f);
    float ik = 1.f / fmaxf(sqrtf(ssk), 1e-12f);
    float* dq = g_qn + ((size_t)(b * cH + h) * cL + l) * cDK;
    float* dk = g_kn + ((size_t)(b * cH + h) * cL + l) * cDK;
#pragma unroll
    for (int r = 0; r < 3; r++) {
        dq[lane + 32 * r] = qv[r] * iq;
        dk[lane + 32 * r] = kv[r] * ik;
    }
}

// ---------------- conv + SiLU for v; writes head layout directly ----------------
__global__ void conv_v_kernel(const float* __restrict__ wv)
{
    int idx = blockIdx.x * blockDim.x + threadIdx.x;
    if (idx >= cM * cVD) return;
    int c = idx % cVD;
    int m = idx / cVD;
    int l = m % cL, b = m / cL;
    float acc = 0.f;
#pragma unroll
    for (int j = 0; j < 4; j++) {
        int ll = l - 3 + j;
        if (ll >= 0) acc += g_proj[(size_t)(m - l + ll) * cNP + 2 * cKD + c] * wv[c * 4 + j];
    }
    int h = c / cDV, d = c % cDV;
    g_vh[((size_t)(b * cH + h) * cL + l) * cDV + d] = acc / (1.f + expf(-acc));
}

// ---------------- per-chunk precompute ----------------
constexpr int CP_SMEM_FLOATS = 3 * 6144 + 4096 + 4096 + 12288 + 64 + 64;
constexpr int CP_THREADS = 320;
__global__ void chunk_pre_kernel()
{
    extern __shared__ float sm[];
    float* sq   = sm;
    float* sk   = sq + 6144;
    float* skb  = sk + 6144;
    float* sKK  = skb + 6144;
    float* sM   = sKK + 4096;
    float* sv   = sM + 4096;
    float* sdec = sv + 12288;
    float* sbet = sdec + 64;

    const int tid = threadIdx.x;
    const int cid = blockIdx.x;           // 0..1023
    const int bh = cid / cNC;
    const int n  = cid % cNC;
    const size_t cbg  = (size_t)bh * cL + n * cCS;
    const size_t cb96  = cbg * cDK;
    const size_t cb192 = cbg * cDV;
    const float scale = rsqrtf((float)cDK);

    for (int i = tid; i < 1536; i += CP_THREADS) {
        ((float4*)sq)[i] = ((const float4*)(g_qn + cb96))[i];
        ((float4*)sk)[i] = ((const float4*)(g_kn + cb96))[i];
    }
    if (tid < 64) sbet[tid] = g_bt[cbg + tid];
    if (tid < 32) {
        float x0 = g_gk[cbg + tid], x1 = g_gk[cbg + 32 + tid];
#pragma unroll
        for (int o = 1; o < 32; o <<= 1) {
            float y = __shfl_up_sync(0xffffffffu, x0, o);
            if (tid >= o) x0 += y;
        }
        float t0 = __shfl_sync(0xffffffffu, x0, 31);
#pragma unroll
        for (int o = 1; o < 32; o <<= 1) {
            float y = __shfl_up_sync(0xffffffffu, x1, o);
            if (tid >= o) x1 += y;
        }
        sdec[tid] = x0;
        sdec[32 + tid] = x1 + t0;
    }
    __syncthreads();
    const float dl = sdec[63];

    for (int i = tid; i < 6144; i += CP_THREADS)  skb[i] = sk[i] * sbet[i / cDK];
    for (int i = tid; i < 12288; i += CP_THREADS) sv[i]  = g_vh[cb192 + i] * sbet[i / cDV];

    // write qe and kd back in place (shared copies keep originals)
    for (int i = tid; i < 6144; i += CP_THREADS) {
        int c = i / cDK;
        g_qn[cb96 + i] = sq[i] * scale * expf(sdec[c]);
        g_kn[cb96 + i] = sk[i] * expf(dl - sdec[c]);
    }
    __syncthreads();

    // KK = kb @ k^T
    for (int idx = tid; idx < 4096; idx += CP_THREADS) {
        int i = idx >> 6, j = idx & 63;
        float s = 0.f;
        const float4* a4 = (const float4*)(skb + i * cDK);
        const float4* b4 = (const float4*)(sk + j * cDK);
#pragma unroll 6
        for (int d = 0; d < cDK / 4; d++) {
            float4 a = a4[d], b = b4[d];
            s += a.x * b.x + a.y * b.y + a.z * b.z + a.w * b.w;
        }
        sKK[idx] = s;
    }
    // intra-chunk attn (incl diagonal)
    for (int idx = tid; idx < 4096; idx += CP_THREADS) {
        int i = idx >> 6, j = idx & 63;
        float a = 0.f;
        if (i >= j) {
            float s = 0.f;
            const float4* a4 = (const float4*)(sq + i * cDK);
            const float4* b4 = (const float4*)(sk + j * cDK);
#pragma unroll 6
            for (int d = 0; d < cDK / 4; d++) {
                float4 x = a4[d], y = b4[d];
                s += x.x * y.x + x.y * y.y + x.z * y.z + x.w * y.w;
            }
            a = s * scale * expf(sdec[i] - sdec[j]);
        }
        g_at[(size_t)cid * 4096 + idx] = a;
    }
    // M1 = KK * Lmask, strict lower
    for (int idx = tid; idx < 4096; idx += CP_THREADS) {
        int i = idx >> 6, j = idx & 63;
        sM[idx] = (i > j) ? sKK[idx] * expf(sdec[i] - sdec[j]) : 0.f;
    }
    __syncthreads();

    // concurrent forward substitutions
    for (int i = 1; i < 64; i++) {
        if (tid < 192) {
            float s = 0.f;
            const float* mrow = sM + i * 64;
            int j = 0;
            for (; j + 4 <= i; j += 4) {
                float4 m4 = *(const float4*)(mrow + j);
                s += m4.x * sv[(j + 0) * 192 + tid] + m4.y * sv[(j + 1) * 192 + tid]
                   + m4.z * sv[(j + 2) * 192 + tid] + m4.w * sv[(j + 3) * 192 + tid];
            }
            for (; j < i; j++) s += mrow[j] * sv[j * 192 + tid];
            sv[i * 192 + tid] -= s;
        } else if (tid < 288) {
            int c = tid - 192;
            float s = 0.f;
            const float* krow = sKK + i * 64;
            int j = 0;
            for (; j + 4 <= i; j += 4) {
                float4 m4 = *(const float4*)(krow + j);
                s += m4.x * skb[(j + 0) * 96 + c] + m4.y * skb[(j + 1) * 96 + c]
                   + m4.z * skb[(j + 2) * 96 + c] + m4.w * skb[(j + 3) * 96 + c];
            }
            for (; j < i; j++) s += krow[j] * skb[j * 96 + c];
            skb[i * 96 + c] -= s;
        }
        __syncthreads();
    }

    for (int i = tid; i < 12288; i += CP_THREADS) g_vh[cb192 + i] = sv[i];
    for (int i = tid; i < 6144; i += CP_THREADS) {
        int c = i / cDK;
        g_kce[cb96 + i] = skb[i] * expf(sdec[c]);
    }
    if (tid == 0) g_edl[cid] = expf(dl);
}

// ---------------- sequential scan over chunks ----------------
// grid (6, 16): x = 32-wide value-column split, y = bh; 1024 threads (32 warps)
constexpr int SC_SMEM_FLOATS = 3 * 6144 + 4096 + 2048 + 2048 + 3072;
constexpr int SC_THREADS = 1024;
__global__ void __launch_bounds__(SC_THREADS, 1)
scan_kernel()
{
    extern __shared__ float sm[];
    float* sqe  = sm;
    float* skce = sqe + 6144;
    float* skd  = skce + 6144;
    float* sat  = skd + 6144;
    float* su   = sat + 4096;
    float* svn  = su + 2048;
    float* S    = svn + 2048;   // 96 x 32

    const int tid = threadIdx.x;
    const int bh = blockIdx.y;
    const int e0 = blockIdx.x * 32;
    const int e  = tid & 31;
    const int w  = tid >> 5;        // 0..31
    const int c0 = w * 2;           // 2 chunk rows per warp
    const int d0 = w * 3;           // 3 state rows per warp

    for (int i = tid; i < 3072; i += SC_THREADS) S[i] = 0.f;

    for (int n = 0; n < cNC; n++) {
        const size_t cbg = (size_t)bh * cL + n * cCS;
        const size_t cb96 = cbg * cDK;
        const size_t cb192 = cbg * cDV;
        __syncthreads();
        for (int i = tid; i < 1536; i += SC_THREADS) {
            ((float4*)sqe)[i]  = ((const float4*)(g_qn + cb96))[i];
            ((float4*)skce)[i] = ((const float4*)(g_kce + cb96))[i];
        }
        for (int i = tid; i < 1536 + 1024; i += SC_THREADS) {
            if (i < 1536) ((float4*)skd)[i] = ((const float4*)(g_kn + cb96))[i];
            else ((float4*)sat)[i - 1536] =
                     ((const float4*)(g_at + (size_t)(bh * cNC + n) * 4096))[i - 1536];
        }
        for (int i = tid; i < 512; i += SC_THREADS) {
            int c = i >> 3, ee = (i & 7) * 4;
            *(float4*)&su[c * 32 + ee] =
                *(const float4*)&g_vh[cb192 + (size_t)c * cDV + e0 + ee];
        }
        __syncthreads();

        // fused: v_new = u - kce@S  AND  o_part = qe@S (read old S once)
        float accv0 = 0.f, accv1 = 0.f, acco0 = 0.f, acco1 = 0.f;
        const float* kce0 = skce + c0 * cDK;
        const float* kce1 = skce + (c0 + 1) * cDK;
        const float* qe0  = sqe + c0 * cDK;
        const float* qe1  = sqe + (c0 + 1) * cDK;
        for (int j = 0; j < cDK; j += 4) {
            float s0 = S[(j + 0) * 32 + e];
            float s1 = S[(j + 1) * 32 + e];
            float s2 = S[(j + 2) * 32 + e];
            float s3 = S[(j + 3) * 32 + e];
            float4 k0 = *(const float4*)(kce0 + j);
            float4 k1 = *(const float4*)(kce1 + j);
            float4 q0 = *(const float4*)(qe0 + j);
            float4 q1 = *(const float4*)(qe1 + j);
            accv0 += k0.x * s0 + k0.y * s1 + k0.z * s2 + k0.w * s3;
            accv1 += k1.x * s0 + k1.y * s1 + k1.z * s2 + k1.w * s3;
            acco0 += q0.x * s0 + q0.y * s1 + q0.z * s2 + q0.w * s3;
            acco1 += q1.x * s0 + q1.y * s1 + q1.z * s2 + q1.w * s3;
        }
        svn[c0 * 32 + e]       = su[c0 * 32 + e] - accv0;
        svn[(c0 + 1) * 32 + e] = su[(c0 + 1) * 32 + e] - accv1;
        __syncthreads();

        // o += attn @ v_new  AND  S = S*exp(dl) + kd^T @ v_new (both read svn)
        const float* at0 = sat + c0 * 64;
        const float* at1 = sat + (c0 + 1) * 64;
        for (int j = 0; j < 64; j += 4) {
            float v0 = svn[(j + 0) * 32 + e];
            float v1 = svn[(j + 1) * 32 + e];
            float v2 = svn[(j + 2) * 32 + e];
            float v3 = svn[(j + 3) * 32 + e];
            float4 a0 = *(const float4*)(at0 + j);
            float4 a1 = *(const float4*)(at1 + j);
            acco0 += a0.x * v0 + a0.y * v1 + a0.z * v2 + a0.w * v3;
            acco1 += a1.x * v0 + a1.y * v1 + a1.z * v2 + a1.w * v3;
        }
        g_o[cb192 + (size_t)c0 * cDV + e0 + e]       = acco0;
        g_o[cb192 + (size_t)(c0 + 1) * cDV + e0 + e] = acco1;

        const float el = g_edl[bh * cNC + n];
        float aS0 = 0.f, aS1 = 0.f, aS2 = 0.f;
        const float* kb = skd + d0;
        for (int c = 0; c < 64; c += 2) {
            float va = svn[c * 32 + e];
            float vb = svn[(c + 1) * 32 + e];
            const float* ka = kb + c * cDK;
            const float* kc = kb + (c + 1) * cDK;
            aS0 += ka[0] * va + kc[0] * vb;
            aS1 += ka[1] * va + kc[1] * vb;
            aS2 += ka[2] * va + kc[2] * vb;
        }
        S[(d0 + 0) * 32 + e] = S[(d0 + 0) * 32 + e] * el + aS0;
        S[(d0 + 1) * 32 + e] = S[(d0 + 1) * 32 + e] * el + aS1;
        S[(d0 + 2) * 32 + e] = S[(d0 + 2) * 32 + e] * el + aS2;
    }
}

// ---------------- gated RMS norm + transpose back (writes tf32 bits) ----------------
__global__ void gate_norm_kernel(const float* __restrict__ norm_w)
{
    int gw = (blockIdx.x * blockDim.x + threadIdx.x) >> 5;
    int lane = threadIdx.x & 31;
    if (gw >= cM * cH) return;
    int m = gw / cH, h = gw % cH;
    int b = m / cL, l = m % cL;
    const float* orow = g_o + ((size_t)(b * cH + h) * cL + l) * cDV;
    float vals[6];
    float ss = 0.f;
#pragma unroll
    for (int k = 0; k < 6; k++) {
        float v = orow[lane + 32 * k];
        vals[k] = v;
        ss += v * v;
    }
#pragma unroll
    for (int o = 16; o; o >>= 1) ss += __shfl_xor_sync(0xffffffffu, ss, o);
    float r = 1.f / sqrtf(ss / (float)cDV + 1e-5f);
#pragma unroll
    for (int k = 0; k < 6; k++) {
        int d = lane + 32 * k;
        float gg = g_proj[(size_t)m * cNP + 2 * cKD + cVD + h * cDV + d];
        float sg = gg / (1.f + expf(-gg));
        g_on[(size_t)m * cVD + h * cDV + d] = f2tf32(vals[k] * r * norm_w[d] * sg);
    }
}

// ---------------- host launch ----------------
template <typename T>
static T* sym(const void* symbol)
{
    void* p = nullptr;
    cudaGetSymbolAddress(&p, symbol);
    return (T*)p;
}

extern "C" void kernel_launch(void* const* d_in, const int* in_sizes, int n_in,
                              void* d_out, int out_size)
{
    const float* u       = (const float*)d_in[0];
    const float* Wq      = (const float*)d_in[1];
    const float* Wk      = (const float*)d_in[2];
    const float* Wv      = (const float*)d_in[3];
    const float* Wg      = (const float*)d_in[4];
    const float* Wo      = (const float*)d_in[5];
    const float* Wgk     = (const float*)d_in[6];
    const float* Wb      = (const float*)d_in[7];
    const float* b_b     = (const float*)d_in[8];
    const float* A_log   = (const float*)d_in[9];
    const float* dt_bias = (const float*)d_in[10];
    const float* conv_q  = (const float*)d_in[11];
    const float* conv_k  = (const float*)d_in[12];
    const float* conv_v  = (const float*)d_in[13];
    const float* norm_w  = (const float*)d_in[14];
    float* out = (float*)d_out;

    uint32_t* Wcat = sym<uint32_t>(g_Wcat);
    uint32_t* WoT  = sym<uint32_t>(g_WoT);
    uint32_t* uT   = sym<uint32_t>(g_uT);
    uint32_t* on   = sym<uint32_t>(g_on);
    float* proj = sym<float>(g_proj);

    cudaFuncSetAttribute(gemm_tf32_kernel, cudaFuncAttributeMaxDynamicSharedMemorySize, GEMM_SMEM);
    cudaFuncSetAttribute(chunk_pre_kernel, cudaFuncAttributeMaxDynamicSharedMemorySize,
                         CP_SMEM_FLOATS * (int)sizeof(float));
    cudaFuncSetAttribute(scan_kernel, cudaFuncAttributeMaxDynamicSharedMemorySize,
                         SC_SMEM_FLOATS * (int)sizeof(float));
    cudaFuncSetAttribute(proj_gates_kernel, cudaFuncAttributeMaxDynamicSharedMemorySize, 65536);

    // pack/convert
    pack_w_kernel<<<(cD * cNP + 255) / 256, 256>>>(Wq, Wk, Wv, Wg);
    convert_u_kernel<<<(cM * cD / 4 + 255) / 256, 256>>>((const float4*)u);
    pack_wo_kernel<<<(cVD * cD + 255) / 256, 256>>>(Wo);

    // fused projection GEMM (q|k|v|g)
    gemm_tf32_kernel<<<dim3(cNP / 128, cM / 128), 256, GEMM_SMEM>>>(
        uT, cD, Wcat, cNP, proj, cNP, cM, cNP, cD);

    // gates
    proj_gates_kernel<<<cM / 8, 256, 65536>>>(u, Wgk, Wb, b_b, A_log, dt_bias);

    // fused conv+silu(+l2norm) -> head layouts
    conv_qk_norm_kernel<<<(cM * cH * 32 + 255) / 256, 256>>>(conv_q, conv_k);
    conv_v_kernel<<<(cM * cVD + 255) / 256, 256>>>(conv_v);

    // delta-rule chunk precompute + scan
    chunk_pre_kernel<<<cBH * cNC, CP_THREADS, CP_SMEM_FLOATS * sizeof(float)>>>();
    scan_kernel<<<dim3(6, cBH), SC_THREADS, SC_SMEM_FLOATS * sizeof(float)>>>();

    // gated rms norm + output projection
    gate_norm_kernel<<<(cM * cH * 32 + 255) / 256, 256>>>(norm_w);
    gemm_tf32_kernel<<<dim3(cD / 128, cM / 128), 256, GEMM_SMEM>>>(
        on, cVD, WoT, cD, out, cD, cM, cD, cVD);
}

// round 7
// speedup vs baseline: 1.2410x; 1.2410x over previous
#include <cuda_runtime.h>
#include <math.h>
#include <stdint.h>

// ---------------- problem constants ----------------
constexpr int cB  = 2;
constexpr int cL  = 4096;
constexpr int cD  = 1024;   // D_MODEL
constexpr int cKD = 768;    // KEY_DIM
constexpr int cVD = 1536;   // VALUE_DIM
constexpr int cH  = 8;
constexpr int cDK = 96;     // per-head qk dim
constexpr int cDV = 192;    // per-head v dim
constexpr int cCS = 64;     // chunk size
constexpr int cNC = cL / cCS;       // 64 chunks per sequence
constexpr int cM  = cB * cL;        // 8192 tokens
constexpr int cBH = cB * cH;        // 16
constexpr int cNP = cKD + cKD + cVD + cVD;  // 4608 packed projection width

// ---------------- scratch (device globals; no cudaMalloc allowed) ----------------
__device__ uint32_t g_Wcat[cD * cNP];   // packed [Wq|Wk|Wv|Wg], tf32 bits
__device__ uint32_t g_WoT [cVD * cD];   // Wo, tf32 bits
__device__ uint32_t g_uT  [cM * cD];    // u, tf32 bits
__device__ float g_proj[cM * cNP];      // packed projection outputs (fp32)
__device__ float g_qn [cM * cKD];   // head layout; becomes qe after chunk_pre
__device__ float g_kn [cM * cKD];   // head layout; becomes kd after chunk_pre
__device__ float g_vh [cM * cVD];   // head layout; becomes u_ after chunk_pre
__device__ float g_kce[cM * cKD];   // kcd * exp(dec)
__device__ float g_gk [cBH * cL];
__device__ float g_bt [cBH * cL];
__device__ float g_at [cBH * cNC * cCS * cCS];  // intra-chunk attn
__device__ float g_edl[cBH * cNC];
__device__ float g_o  [cM * cVD];   // (b,h,l,dv)
__device__ uint32_t g_on [cM * cVD];   // gated+normed, tf32 bits

// ---------------- tf32 helpers ----------------
__device__ __forceinline__ uint32_t f2tf32(float f)
{
    uint32_t r;
    asm("cvt.rna.tf32.f32 %0, %1;" : "=r"(r) : "f"(f));
    return r;
}

__device__ __forceinline__ void mma_tf32(float c[4], const uint32_t a[4], const uint32_t b[2])
{
    asm volatile(
        "mma.sync.aligned.m16n8k8.row.col.f32.tf32.tf32.f32 "
        "{%0,%1,%2,%3}, {%4,%5,%6,%7}, {%8,%9}, {%0,%1,%2,%3};"
        : "+f"(c[0]), "+f"(c[1]), "+f"(c[2]), "+f"(c[3])
        : "r"(a[0]), "r"(a[1]), "r"(a[2]), "r"(a[3]), "r"(b[0]), "r"(b[1]));
}

#define CP16(dst, src) \
    asm volatile("cp.async.cg.shared.global [%0], [%1], 16;" :: "r"(dst), "l"(src))

// ---------------- tf32 tensor-core GEMM (4-stage cp.async pipeline) ----------------
// C[M,N] = A[M,K] @ B[K,N], A/B already tf32 bit-patterns, row-major.
// M%128==0, N%128==0, K%16==0, K/16 >= 4. Dynamic smem: 75776 bytes.
constexpr int GEMM_SMEM = 4 * (128 * 20 + 16 * 136) * 4;
__global__ void __launch_bounds__(256, 2)
gemm_tf32_kernel(const uint32_t* __restrict__ A, int lda,
                 const uint32_t* __restrict__ B, int ldb,
                 float* __restrict__ C, int ldc,
                 int M, int N, int K)
{
    extern __shared__ uint32_t smem_u[];
    typedef uint32_t AsT[128][20];
    typedef uint32_t BsT[16][136];
    AsT* As = (AsT*)smem_u;
    BsT* Bs = (BsT*)(smem_u + 4 * 128 * 20);

    const int tid  = threadIdx.x;
    const int wid  = tid >> 5;
    const int lane = tid & 31;
    const int g    = lane >> 2;
    const int t    = lane & 3;
    const int wm   = (wid >> 2) * 64;
    const int wn   = (wid & 3) * 32;

    const int bm = blockIdx.y * 128;
    const int bn = blockIdx.x * 128;

    const int arow = tid >> 1;
    const int akb  = (tid & 1) * 8;
    const int bkr  = tid >> 4;
    const int bnb  = (tid & 15) * 8;

    const uint32_t* Ag = A + (size_t)(bm + arow) * lda + akb;
    const uint32_t* Bg = B + (size_t)bkr * ldb + bn + bnb;

    uint32_t sa[4], sb[4];
#pragma unroll
    for (int s = 0; s < 4; s++) {
        sa[s] = (uint32_t)__cvta_generic_to_shared(&As[s][arow][akb]);
        sb[s] = (uint32_t)__cvta_generic_to_shared(&Bs[s][bkr][bnb]);
    }

    float acc[4][4][4];
#pragma unroll
    for (int i = 0; i < 4; i++)
#pragma unroll
        for (int j = 0; j < 4; j++)
#pragma unroll
            for (int r = 0; r < 4; r++) acc[i][j][r] = 0.f;

    const int nt = K >> 4;

#pragma unroll
    for (int s = 0; s < 3; s++) {
        const uint32_t* a = Ag + (size_t)s * 16;
        const uint32_t* b = Bg + (size_t)s * 16 * ldb;
        CP16(sa[s], a); CP16(sa[s] + 16, a + 4);
        CP16(sb[s], b); CP16(sb[s] + 16, b + 4);
        asm volatile("cp.async.commit_group;");
    }

    for (int kt = 0; kt < nt; kt++) {
        asm volatile("cp.async.wait_group 2;");
        __syncthreads();

        const int buf = kt & 3;
#pragma unroll
        for (int ks = 0; ks < 16; ks += 8) {
            uint32_t af[4][4], bf[4][2];
#pragma unroll
            for (int mi = 0; mi < 4; mi++) {
                int mr = wm + mi * 16;
                af[mi][0] = As[buf][mr + g][ks + t];
                af[mi][1] = As[buf][mr + g + 8][ks + t];
                af[mi][2] = As[buf][mr + g][ks + t + 4];
                af[mi][3] = As[buf][mr + g + 8][ks + t + 4];
            }
#pragma unroll
            for (int ni = 0; ni < 4; ni++) {
                int nc = wn + ni * 8;
                bf[ni][0] = Bs[buf][ks + t][nc + g];
                bf[ni][1] = Bs[buf][ks + t + 4][nc + g];
            }
#pragma unroll
            for (int mi = 0; mi < 4; mi++)
#pragma unroll
                for (int ni = 0; ni < 4; ni++)
                    mma_tf32(acc[mi][ni], af[mi], bf[ni]);
        }

        if (kt + 3 < nt) {
            const int s = (kt + 3) & 3;
            const uint32_t* a = Ag + (size_t)(kt + 3) * 16;
            const uint32_t* b = Bg + (size_t)(kt + 3) * 16 * ldb;
            CP16(sa[s], a); CP16(sa[s] + 16, a + 4);
            CP16(sb[s], b); CP16(sb[s] + 16, b + 4);
        }
        asm volatile("cp.async.commit_group;");
    }

#pragma unroll
    for (int mi = 0; mi < 4; mi++) {
#pragma unroll
        for (int ni = 0; ni < 4; ni++) {
            int row0 = bm + wm + mi * 16 + g;
            int col  = bn + wn + ni * 8 + 2 * t;
            *(float2*)(C + (size_t)row0 * ldc + col) = make_float2(acc[mi][ni][0], acc[mi][ni][1]);
            *(float2*)(C + (size_t)(row0 + 8) * ldc + col) = make_float2(acc[mi][ni][2], acc[mi][ni][3]);
        }
    }
}

// ---------------- pack [Wq|Wk|Wv|Wg] into one tf32 matrix ----------------
__global__ void pack_w_kernel(const float* __restrict__ Wq, const float* __restrict__ Wk,
                              const float* __restrict__ Wv, const float* __restrict__ Wg)
{
    int idx = blockIdx.x * blockDim.x + threadIdx.x;
    if (idx >= cD * cNP) return;
    int row = idx / cNP, col = idx % cNP;
    float v;
    if (col < cKD)            v = Wq[row * cKD + col];
    else if (col < 2 * cKD)   v = Wk[row * cKD + col - cKD];
    else if (col < 2 * cKD + cVD) v = Wv[row * cVD + col - 2 * cKD];
    else                      v = Wg[row * cVD + col - 2 * cKD - cVD];
    g_Wcat[idx] = f2tf32(v);
}

__global__ void pack_wo_kernel(const float* __restrict__ Wo)
{
    int idx = blockIdx.x * blockDim.x + threadIdx.x;
    if (idx >= cVD * cD) return;
    g_WoT[idx] = f2tf32(Wo[idx]);
}

__global__ void convert_u_kernel(const float4* __restrict__ u4)
{
    int idx = blockIdx.x * blockDim.x + threadIdx.x;
    if (idx >= cM * cD / 4) return;
    float4 v = u4[idx];
    uint4 r;
    r.x = f2tf32(v.x); r.y = f2tf32(v.y); r.z = f2tf32(v.z); r.w = f2tf32(v.w);
    ((uint4*)g_uT)[idx] = r;
}

// ---------------- gk / beta projections: warp per token, W in smem ----------------
__global__ void proj_gates_kernel(const float* __restrict__ u, const float* __restrict__ Wgk,
                                  const float* __restrict__ Wb, const float* __restrict__ b_b,
                                  const float* __restrict__ A_log, const float* __restrict__ dt_bias)
{
    extern __shared__ float sW[];   // [1024][16]
    const int tid = threadIdx.x;
    const int wid = tid >> 5;
    const int lane = tid & 31;

    for (int idx = tid; idx < cD * 16; idx += 256) {
        int i = idx >> 4, c = idx & 15;
        sW[idx] = (c < 8) ? Wgk[i * cH + c] : Wb[i * cH + (c - 8)];
    }
    __syncthreads();

    int m = blockIdx.x * 8 + wid;
    const float* ur = u + (size_t)m * cD;
    float s[16];
#pragma unroll
    for (int c = 0; c < 16; c++) s[c] = 0.f;
    for (int j = 0; j < 32; j++) {
        int i = lane + 32 * j;
        float uv = __ldg(ur + i);
        const float* wr = sW + i * 16;
#pragma unroll
        for (int c = 0; c < 16; c++) s[c] += uv * wr[c];
    }
#pragma unroll
    for (int c = 0; c < 16; c++) {
#pragma unroll
        for (int o = 16; o; o >>= 1) s[c] += __shfl_xor_sync(0xffffffffu, s[c], o);
    }
    if (lane < 8) {
        int h = lane;
        float x  = s[h] + dt_bias[h];
        float sp = (x > 20.f) ? x : log1pf(expf(x));
        float gkv = -expf(A_log[h]) * sp;
        int b = m / cL, l = m % cL;
        g_gk[((size_t)(b * cH + h)) * cL + l] = gkv;
    } else {
        int h = lane - 8;
        float bv = 1.f / (1.f + expf(-(s[8 + h] + b_b[h])));
        int b = m / cL, l = m % cL;
        g_bt[((size_t)(b * cH + h)) * cL + l] = bv;
    }
}

// ---------------- fused conv + SiLU + L2norm for q,k; writes head layout ----------------
__global__ void conv_qk_norm_kernel(const float* __restrict__ wq, const float* __restrict__ wk)
{
    int gw = (blockIdx.x * blockDim.x + threadIdx.x) >> 5;
    int lane = threadIdx.x & 31;
    if (gw >= cM * cH) return;
    int m = gw / cH, h = gw % cH;
    int b = m / cL, l = m % cL;
    const size_t rowbase = (size_t)(m - l) * cNP;

    float qv[3], kv[3];
    float ssq = 0.f, ssk = 0.f;
#pragma unroll
    for (int r = 0; r < 3; r++) {
        int c = h * cDK + lane + 32 * r;
        float aq = 0.f, ak = 0.f;
#pragma unroll
        for (int j = 0; j < 4; j++) {
            int ll = l - 3 + j;
            if (ll >= 0) {
                const float* row = g_proj + rowbase + (size_t)ll * cNP;
                aq += row[c]       * wq[c * 4 + j];
                ak += row[cKD + c] * wk[c * 4 + j];
            }
        }
        aq = aq / (1.f + expf(-aq));
        ak = ak / (1.f + expf(-ak));
        qv[r] = aq; kv[r] = ak;
        ssq += aq * aq; ssk += ak * ak;
    }
#pragma unroll
    for (int o = 16; o; o >>= 1) {
        ssq += __shfl_xor_sync(0xffffffffu, ssq, o);
        ssk += __shfl_xor_sync(0xffffffffu, ssk, o);
    }
    float iq = 1.f / fmaxf(sqrtf(ssq), 1e-12f);
    float ik = 1.f / fmaxf(sqrtf(ssk), 1e-12f);
    float* dq = g_qn + ((size_t)(b * cH + h) * cL + l) * cDK;
    float* dk = g_kn + ((size_t)(b * cH + h) * cL + l) * cDK;
#pragma unroll
    for (int r = 0; r < 3; r++) {
        dq[lane + 32 * r] = qv[r] * iq;
        dk[lane + 32 * r] = kv[r] * ik;
    }
}

// ---------------- conv + SiLU for v; writes head layout directly ----------------
__global__ void conv_v_kernel(const float* __restrict__ wv)
{
    int idx = blockIdx.x * blockDim.x + threadIdx.x;
    if (idx >= cM * cVD) return;
    int c = idx % cVD;
    int m = idx / cVD;
    int l = m % cL, b = m / cL;
    float acc = 0.f;
#pragma unroll
    for (int j = 0; j < 4; j++) {
        int ll = l - 3 + j;
        if (ll >= 0) acc += g_proj[(size_t)(m - l + ll) * cNP + 2 * cKD + c] * wv[c * 4 + j];
    }
    int h = c / cDV, d = c % cDV;
    g_vh[((size_t)(b * cH + h) * cL + l) * cDV + d] = acc / (1.f + expf(-acc));
}

// ---------------- per-chunk precompute (sk padded to stride 100: no 32-way conflicts) ----------------
constexpr int cSKS = 100;   // padded row stride for sk (gcd(100,32)=4 -> 4-phase float4, the minimum)
constexpr int CP_SMEM_FLOATS = 6144 + 64 * cSKS + 6144 + 4096 + 4096 + 12288 + 64 + 64;
constexpr int CP_THREADS = 320;
__global__ void chunk_pre_kernel()
{
    extern __shared__ float sm[];
    float* sq   = sm;                    // 64 x 96
    float* sk   = sq + 6144;             // 64 x 100 (padded)
    float* skb  = sk + 64 * cSKS;        // 64 x 96
    float* sKK  = skb + 6144;            // 64 x 64
    float* sM   = sKK + 4096;            // 64 x 64
    float* sv   = sM + 4096;             // 64 x 192
    float* sdec = sv + 12288;
    float* sbet = sdec + 64;

    const int tid = threadIdx.x;
    const int cid = blockIdx.x;           // 0..1023
    const int bh = cid / cNC;
    const int n  = cid % cNC;
    const size_t cbg  = (size_t)bh * cL + n * cCS;
    const size_t cb96  = cbg * cDK;
    const size_t cb192 = cbg * cDV;
    const float scale = rsqrtf((float)cDK);

    for (int i4 = tid; i4 < 1536; i4 += CP_THREADS) {
        ((float4*)sq)[i4] = ((const float4*)(g_qn + cb96))[i4];
        int c = i4 / 24, d4 = i4 % 24;
        ((float4*)sk)[c * (cSKS / 4) + d4] = ((const float4*)(g_kn + cb96))[i4];
    }
    if (tid < 64) sbet[tid] = g_bt[cbg + tid];
    if (tid < 32) {
        float x0 = g_gk[cbg + tid], x1 = g_gk[cbg + 32 + tid];
#pragma unroll
        for (int o = 1; o < 32; o <<= 1) {
            float y = __shfl_up_sync(0xffffffffu, x0, o);
            if (tid >= o) x0 += y;
        }
        float t0 = __shfl_sync(0xffffffffu, x0, 31);
#pragma unroll
        for (int o = 1; o < 32; o <<= 1) {
            float y = __shfl_up_sync(0xffffffffu, x1, o);
            if (tid >= o) x1 += y;
        }
        sdec[tid] = x0;
        sdec[32 + tid] = x1 + t0;
    }
    __syncthreads();
    const float dl = sdec[63];

    for (int i = tid; i < 6144; i += CP_THREADS) {
        int c = i / cDK, d = i - c * cDK;
        skb[i] = sk[c * cSKS + d] * sbet[c];
    }
    for (int i = tid; i < 12288; i += CP_THREADS) sv[i]  = g_vh[cb192 + i] * sbet[i / cDV];

    // write qe and kd back in place (shared copies keep originals)
    for (int i = tid; i < 6144; i += CP_THREADS) {
        int c = i / cDK, d = i - c * cDK;
        g_qn[cb96 + i] = sq[i] * scale * expf(sdec[c]);
        g_kn[cb96 + i] = sk[c * cSKS + d] * expf(dl - sdec[c]);
    }
    __syncthreads();

    // KK = kb @ k^T  (skb row broadcast, sk j-side padded -> 4-phase float4)
    for (int idx = tid; idx < 4096; idx += CP_THREADS) {
        int i = idx >> 6, j = idx & 63;
        float s = 0.f;
        const float4* a4 = (const float4*)(skb + i * cDK);
        const float4* b4 = (const float4*)(sk + j * cSKS);
#pragma unroll 6
        for (int d = 0; d < cDK / 4; d++) {
            float4 a = a4[d], b = b4[d];
            s += a.x * b.x + a.y * b.y + a.z * b.z + a.w * b.w;
        }
        sKK[idx] = s;
    }
    // intra-chunk attn (incl diagonal)
    for (int idx = tid; idx < 4096; idx += CP_THREADS) {
        int i = idx >> 6, j = idx & 63;
        float a = 0.f;
        if (i >= j) {
            float s = 0.f;
            const float4* a4 = (const float4*)(sq + i * cDK);
            const float4* b4 = (const float4*)(sk + j * cSKS);
#pragma unroll 6
            for (int d = 0; d < cDK / 4; d++) {
                float4 x = a4[d], y = b4[d];
                s += x.x * y.x + x.y * y.y + x.z * y.z + x.w * y.w;
            }
            a = s * scale * expf(sdec[i] - sdec[j]);
        }
        g_at[(size_t)cid * 4096 + idx] = a;
    }
    // M1 = KK * Lmask, strict lower
    for (int idx = tid; idx < 4096; idx += CP_THREADS) {
        int i = idx >> 6, j = idx & 63;
        sM[idx] = (i > j) ? sKK[idx] * expf(sdec[i] - sdec[j]) : 0.f;
    }
    __syncthreads();

    // concurrent forward substitutions
    for (int i = 1; i < 64; i++) {
        if (tid < 192) {
            float s = 0.f;
            const float* mrow = sM + i * 64;
            int j = 0;
            for (; j + 4 <= i; j += 4) {
                float4 m4 = *(const float4*)(mrow + j);
                s += m4.x * sv[(j + 0) * 192 + tid] + m4.y * sv[(j + 1) * 192 + tid]
                   + m4.z * sv[(j + 2) * 192 + tid] + m4.w * sv[(j + 3) * 192 + tid];
            }
            for (; j < i; j++) s += mrow[j] * sv[j * 192 + tid];
            sv[i * 192 + tid] -= s;
        } else if (tid < 288) {
            int c = tid - 192;
            float s = 0.f;
            const float* krow = sKK + i * 64;
            int j = 0;
            for (; j + 4 <= i; j += 4) {
                float4 m4 = *(const float4*)(krow + j);
                s += m4.x * skb[(j + 0) * 96 + c] + m4.y * skb[(j + 1) * 96 + c]
                   + m4.z * skb[(j + 2) * 96 + c] + m4.w * skb[(j + 3) * 96 + c];
            }
            for (; j < i; j++) s += krow[j] * skb[j * 96 + c];
            skb[i * 96 + c] -= s;
        }
        __syncthreads();
    }

    for (int i = tid; i < 12288; i += CP_THREADS) g_vh[cb192 + i] = sv[i];
    for (int i = tid; i < 6144; i += CP_THREADS) {
        int c = i / cDK;
        g_kce[cb96 + i] = skb[i] * expf(sdec[c]);
    }
    if (tid == 0) g_edl[cid] = expf(dl);
}

// ---------------- sequential scan over chunks ----------------
// grid (6, 16): x = 32-wide value-column split, y = bh; 512 threads
constexpr int SC_SMEM_FLOATS = 3 * 6144 + 4096 + 2048 + 2048 + 3072;
constexpr int SC_THREADS = 512;
__global__ void scan_kernel()
{
    extern __shared__ float sm[];
    float* sqe  = sm;
    float* skce = sqe + 6144;
    float* skd  = skce + 6144;
    float* sat  = skd + 6144;
    float* su   = sat + 4096;
    float* svn  = su + 2048;
    float* S    = svn + 2048;   // 96 x 32

    const int tid = threadIdx.x;
    const int bh = blockIdx.y;
    const int e0 = blockIdx.x * 32;
    const int e  = tid & 31;
    const int w  = tid >> 5;
    const int c0 = w * 4;
    const int d0 = w * 6;

    for (int i = tid; i < 3072; i += SC_THREADS) S[i] = 0.f;

    for (int n = 0; n < cNC; n++) {
        const size_t cbg = (size_t)bh * cL + n * cCS;
        const size_t cb96 = cbg * cDK;
        const size_t cb192 = cbg * cDV;
        __syncthreads();
        for (int i = tid; i < 1536; i += SC_THREADS) {
            ((float4*)sqe)[i]  = ((const float4*)(g_qn + cb96))[i];
            ((float4*)skce)[i] = ((const float4*)(g_kce + cb96))[i];
            ((float4*)skd)[i]  = ((const float4*)(g_kn + cb96))[i];
        }
        for (int i = tid; i < 1024; i += SC_THREADS)
            ((float4*)sat)[i] = ((const float4*)(g_at + (size_t)(bh * cNC + n) * 4096))[i];
        for (int i = tid; i < 512; i += SC_THREADS) {
            int c = i >> 3, ee = (i & 7) * 4;
            *(float4*)&su[c * 32 + ee] =
                *(const float4*)&g_vh[cb192 + (size_t)c * cDV + e0 + ee];
        }
        __syncthreads();

        // fused: v_new = u - kce@S  AND  o_part = qe@S (read old S once)
        float accv[4], acco[4];
#pragma unroll
        for (int i = 0; i < 4; i++) { accv[i] = 0.f; acco[i] = 0.f; }
        for (int j = 0; j < cDK; j += 4) {
            float s0 = S[(j + 0) * 32 + e];
            float s1 = S[(j + 1) * 32 + e];
            float s2 = S[(j + 2) * 32 + e];
            float s3 = S[(j + 3) * 32 + e];
#pragma unroll
            for (int i = 0; i < 4; i++) {
                float4 kv = *(const float4*)&skce[(c0 + i) * cDK + j];
                float4 qv = *(const float4*)&sqe[(c0 + i) * cDK + j];
                accv[i] += kv.x * s0 + kv.y * s1 + kv.z * s2 + kv.w * s3;
                acco[i] += qv.x * s0 + qv.y * s1 + qv.z * s2 + qv.w * s3;
            }
        }
#pragma unroll
        for (int i = 0; i < 4; i++) svn[(c0 + i) * 32 + e] = su[(c0 + i) * 32 + e] - accv[i];
        __syncthreads();

        // o += attn @ v_new
        for (int j = 0; j < 64; j += 4) {
            float v0 = svn[(j + 0) * 32 + e];
            float v1 = svn[(j + 1) * 32 + e];
            float v2 = svn[(j + 2) * 32 + e];
            float v3 = svn[(j + 3) * 32 + e];
#pragma unroll
            for (int i = 0; i < 4; i++) {
                float4 av = *(const float4*)&sat[(c0 + i) * 64 + j];
                acco[i] += av.x * v0 + av.y * v1 + av.z * v2 + av.w * v3;
            }
        }
#pragma unroll
        for (int i = 0; i < 4; i++)
            g_o[cb192 + (size_t)(c0 + i) * cDV + e0 + e] = acco[i];

        // S = S*exp(dl) + kd^T @ v_new
        const float el = g_edl[bh * cNC + n];
        float accS[6];
#pragma unroll
        for (int ii = 0; ii < 6; ii++) accS[ii] = 0.f;
        for (int c = 0; c < 64; c++) {
            float v = svn[c * 32 + e];
            const float* kr = skd + c * cDK + d0;
            float2 k0 = *(const float2*)(kr);
            float2 k1 = *(const float2*)(kr + 2);
            float2 k2 = *(const float2*)(kr + 4);
            accS[0] += k0.x * v; accS[1] += k0.y * v;
            accS[2] += k1.x * v; accS[3] += k1.y * v;
            accS[4] += k2.x * v; accS[5] += k2.y * v;
        }
#pragma unroll
        for (int ii = 0; ii < 6; ii++) {
            int idx = (d0 + ii) * 32 + e;
            S[idx] = S[idx] * el + accS[ii];
        }
    }
}

// ---------------- gated RMS norm + transpose back (writes tf32 bits) ----------------
__global__ void gate_norm_kernel(const float* __restrict__ norm_w)
{
    int gw = (blockIdx.x * blockDim.x + threadIdx.x) >> 5;
    int lane = threadIdx.x & 31;
    if (gw >= cM * cH) return;
    int m = gw / cH, h = gw % cH;
    int b = m / cL, l = m % cL;
    const float* orow = g_o + ((size_t)(b * cH + h) * cL + l) * cDV;
    float vals[6];
    float ss = 0.f;
#pragma unroll
    for (int k = 0; k < 6; k++) {
        float v = orow[lane + 32 * k];
        vals[k] = v;
        ss += v * v;
    }
#pragma unroll
    for (int o = 16; o; o >>= 1) ss += __shfl_xor_sync(0xffffffffu, ss, o);
    float r = 1.f / sqrtf(ss / (float)cDV + 1e-5f);
#pragma unroll
    for (int k = 0; k < 6; k++) {
        int d = lane + 32 * k;
        float gg = g_proj[(size_t)m * cNP + 2 * cKD + cVD + h * cDV + d];
        float sg = gg / (1.f + expf(-gg));
        g_on[(size_t)m * cVD + h * cDV + d] = f2tf32(vals[k] * r * norm_w[d] * sg);
    }
}

// ---------------- host launch ----------------
template <typename T>
static T* sym(const void* symbol)
{
    void* p = nullptr;
    cudaGetSymbolAddress(&p, symbol);
    return (T*)p;
}

extern "C" void kernel_launch(void* const* d_in, const int* in_sizes, int n_in,
                              void* d_out, int out_size)
{
    const float* u       = (const float*)d_in[0];
    const float* Wq      = (const float*)d_in[1];
    const float* Wk      = (const float*)d_in[2];
    const float* Wv      = (const float*)d_in[3];
    const float* Wg      = (const float*)d_in[4];
    const float* Wo      = (const float*)d_in[5];
    const float* Wgk     = (const float*)d_in[6];
    const float* Wb      = (const float*)d_in[7];
    const float* b_b     = (const float*)d_in[8];
    const float* A_log   = (const float*)d_in[9];
    const float* dt_bias = (const float*)d_in[10];
    const float* conv_q  = (const float*)d_in[11];
    const float* conv_k  = (const float*)d_in[12];
    const float* conv_v  = (const float*)d_in[13];
    const float* norm_w  = (const float*)d_in[14];
    float* out = (float*)d_out;

    uint32_t* Wcat = sym<uint32_t>(g_Wcat);
    uint32_t* WoT  = sym<uint32_t>(g_WoT);
    uint32_t* uT   = sym<uint32_t>(g_uT);
    uint32_t* on   = sym<uint32_t>(g_on);
    float* proj = sym<float>(g_proj);

    cudaFuncSetAttribute(gemm_tf32_kernel, cudaFuncAttributeMaxDynamicSharedMemorySize, GEMM_SMEM);
    cudaFuncSetAttribute(chunk_pre_kernel, cudaFuncAttributeMaxDynamicSharedMemorySize,
                         CP_SMEM_FLOATS * (int)sizeof(float));
    cudaFuncSetAttribute(scan_kernel, cudaFuncAttributeMaxDynamicSharedMemorySize,
                         SC_SMEM_FLOATS * (int)sizeof(float));
    cudaFuncSetAttribute(proj_gates_kernel, cudaFuncAttributeMaxDynamicSharedMemorySize, 65536);

    // pack/convert
    pack_w_kernel<<<(cD * cNP + 255) / 256, 256>>>(Wq, Wk, Wv, Wg);
    convert_u_kernel<<<(cM * cD / 4 + 255) / 256, 256>>>((const float4*)u);
    pack_wo_kernel<<<(cVD * cD + 255) / 256, 256>>>(Wo);

    // fused projection GEMM (q|k|v|g)
    gemm_tf32_kernel<<<dim3(cNP / 128, cM / 128), 256, GEMM_SMEM>>>(
        uT, cD, Wcat, cNP, proj, cNP, cM, cNP, cD);

    // gates
    proj_gates_kernel<<<cM / 8, 256, 65536>>>(u, Wgk, Wb, b_b, A_log, dt_bias);

    // fused conv+silu(+l2norm) -> head layouts
    conv_qk_norm_kernel<<<(cM * cH * 32 + 255) / 256, 256>>>(conv_q, conv_k);
    conv_v_kernel<<<(cM * cVD + 255) / 256, 256>>>(conv_v);

    // delta-rule chunk precompute + scan
    chunk_pre_kernel<<<cBH * cNC, CP_THREADS, CP_SMEM_FLOATS * sizeof(float)>>>();
    scan_kernel<<<dim3(6, cBH), SC_THREADS, SC_SMEM_FLOATS * sizeof(float)>>>();

    // gated rms norm + output projection
    gate_norm_kernel<<<(cM * cH * 32 + 255) / 256, 256>>>(norm_w);
    gemm_tf32_kernel<<<dim3(cD / 128, cM / 128), 256, GEMM_SMEM>>>(
        on, cVD, WoT, cD, out, cD, cM, cD, cVD);
}

// round 8
// speedup vs baseline: 1.2594x; 1.0148x over previous
#include <cuda_runtime.h>
#include <math.h>
#include <stdint.h>

// ---------------- problem constants ----------------
constexpr int cB  = 2;
constexpr int cL  = 4096;
constexpr int cD  = 1024;   // D_MODEL
constexpr int cKD = 768;    // KEY_DIM
constexpr int cVD = 1536;   // VALUE_DIM
constexpr int cH  = 8;
constexpr int cDK = 96;     // per-head qk dim
constexpr int cDV = 192;    // per-head v dim
constexpr int cCS = 64;     // chunk size
constexpr int cNC = cL / cCS;       // 64 chunks per sequence
constexpr int cM  = cB * cL;        // 8192 tokens
constexpr int cBH = cB * cH;        // 16
constexpr int cNP = cKD + cKD + cVD + cVD;  // 4608 packed projection width

// ---------------- scratch (device globals; no cudaMalloc allowed) ----------------
__device__ uint32_t g_Wcat[cNP * cD];   // [Wq|Wk|Wv|Wg] TRANSPOSED (n-major), tf32 bits
__device__ uint32_t g_WoT [cD * cVD];   // Wo TRANSPOSED (n-major), tf32 bits
__device__ uint32_t g_uT  [cM * cD];    // u, tf32 bits
__device__ float g_proj[cM * cNP];      // packed projection outputs (fp32)
__device__ float g_qn [cM * cKD];   // head layout; becomes qe after chunk_pre
__device__ float g_kn [cM * cKD];   // head layout; becomes kd after chunk_pre
__device__ float g_vh [cM * cVD];   // head layout; becomes u_ after chunk_pre
__device__ float g_kce[cM * cKD];   // kcd * exp(dec)
__device__ float g_gk [cBH * cL];
__device__ float g_bt [cBH * cL];
__device__ float g_at [cBH * cNC * cCS * cCS];  // intra-chunk attn
__device__ float g_edl[cBH * cNC];
__device__ float g_o  [cM * cVD];   // (b,h,l,dv)
__device__ uint32_t g_on [cM * cVD];   // gated+normed, tf32 bits

// ---------------- tf32 helpers ----------------
__device__ __forceinline__ uint32_t f2tf32(float f)
{
    uint32_t r;
    asm("cvt.rna.tf32.f32 %0, %1;" : "=r"(r) : "f"(f));
    return r;
}

__device__ __forceinline__ void mma_tf32(float c[4], const uint32_t a[4], const uint32_t b[2])
{
    asm volatile(
        "mma.sync.aligned.m16n8k8.row.col.f32.tf32.tf32.f32 "
        "{%0,%1,%2,%3}, {%4,%5,%6,%7}, {%8,%9}, {%0,%1,%2,%3};"
        : "+f"(c[0]), "+f"(c[1]), "+f"(c[2]), "+f"(c[3])
        : "r"(a[0]), "r"(a[1]), "r"(a[2]), "r"(a[3]), "r"(b[0]), "r"(b[1]));
}

#define CP16(dst, src) \
    asm volatile("cp.async.cg.shared.global [%0], [%1], 16;" :: "r"(dst), "l"(src))

#define LDSM4(r0, r1, r2, r3, addr) \
    asm volatile("ldmatrix.sync.aligned.m8n8.x4.shared.b16 {%0,%1,%2,%3}, [%4];" \
                 : "=r"(r0), "=r"(r1), "=r"(r2), "=r"(r3) : "r"(addr))

// ---------------- tf32 tensor-core GEMM (cp.async + ldmatrix) ----------------
// C[M,N] = A[M,K] @ B'[N,K]^T; A row-major [M][K], B' row-major [N][K] (pre-transposed).
// ldb must equal K. M%128==0, N%128==0, K%16==0, K/16 >= 4. Dyn smem: 81920 B.
constexpr int GEMM_STAGES = 4;
constexpr int GEMM_STAGE_WORDS = 128 * 20;          // one tile (A or B) per stage
constexpr int GEMM_SMEM = GEMM_STAGES * 2 * GEMM_STAGE_WORDS * 4;
__global__ void __launch_bounds__(256, 2)
gemm_tf32_kernel(const uint32_t* __restrict__ A, int lda,
                 const uint32_t* __restrict__ B, int ldb,
                 float* __restrict__ C, int ldc,
                 int M, int N, int K)
{
    extern __shared__ uint32_t smem_u[];
    uint32_t* As = smem_u;                                   // [stage][128 m][20]
    uint32_t* Bs = smem_u + GEMM_STAGES * GEMM_STAGE_WORDS;  // [stage][128 n][20]

    const int tid  = threadIdx.x;
    const int wid  = tid >> 5;
    const int lane = tid & 31;
    const int g    = lane >> 2;
    const int t    = lane & 3;
    const int wm   = (wid >> 2) * 64;
    const int wn   = (wid & 3) * 32;

    const int bm = blockIdx.y * 128;
    const int bn = blockIdx.x * 128;

    // global staging: each thread covers 32B of one 64B row-chunk
    const int row = tid >> 1;
    const int cb  = (tid & 1) * 8;
    const uint32_t* Ag = A + (size_t)(bm + row) * lda + cb;
    const uint32_t* Bg = B + (size_t)(bn + row) * ldb + cb;

    const uint32_t sA0 = (uint32_t)__cvta_generic_to_shared(As + row * 20 + cb);
    const uint32_t sB0 = (uint32_t)__cvta_generic_to_shared(Bs + row * 20 + cb);
    constexpr uint32_t STG_B = GEMM_STAGE_WORDS * 4;  // stage stride in bytes

    // ldmatrix lane addressing (quadrant layout of m16n8k8 tf32 fragments)
    const int rA = wm + ((lane >> 3) & 1) * 8 + (lane & 7);
    const int cA = (lane >> 4) * 4;
    const int rB = wn + (lane >> 4) * 8 + (lane & 7);
    const int cB2 = ((lane >> 3) & 1) * 4;
    const uint32_t lA0 = (uint32_t)__cvta_generic_to_shared(As + rA * 20 + cA);
    const uint32_t lB0 = (uint32_t)__cvta_generic_to_shared(Bs + rB * 20 + cB2);

    float acc[4][4][4];
#pragma unroll
    for (int i = 0; i < 4; i++)
#pragma unroll
        for (int j = 0; j < 4; j++)
#pragma unroll
            for (int r = 0; r < 4; r++) acc[i][j][r] = 0.f;

    const int nt = K >> 4;

#pragma unroll
    for (int s = 0; s < GEMM_STAGES - 1; s++) {
        const uint32_t* a = Ag + (size_t)s * 16;
        const uint32_t* b = Bg + (size_t)s * 16;
        CP16(sA0 + s * STG_B, a); CP16(sA0 + s * STG_B + 16, a + 4);
        CP16(sB0 + s * STG_B, b); CP16(sB0 + s * STG_B + 16, b + 4);
        asm volatile("cp.async.commit_group;");
    }

    for (int kt = 0; kt < nt; kt++) {
        asm volatile("cp.async.wait_group 2;");
        __syncthreads();

        const int buf = kt & (GEMM_STAGES - 1);
        const uint32_t offA = lA0 + buf * STG_B;
        const uint32_t offB = lB0 + buf * STG_B;
#pragma unroll
        for (int ks = 0; ks < 16; ks += 8) {
            uint32_t af[4][4], bf[4][2];
#pragma unroll
            for (int mi = 0; mi < 4; mi++)
                LDSM4(af[mi][0], af[mi][1], af[mi][2], af[mi][3],
                      offA + mi * (16 * 20 * 4) + ks * 4);
#pragma unroll
            for (int np = 0; np < 2; np++)
                LDSM4(bf[2 * np][0], bf[2 * np][1], bf[2 * np + 1][0], bf[2 * np + 1][1],
                      offB + np * (16 * 20 * 4) + ks * 4);
#pragma unroll
            for (int mi = 0; mi < 4; mi++)
#pragma unroll
                for (int ni = 0; ni < 4; ni++)
                    mma_tf32(acc[mi][ni], af[mi], bf[ni]);
        }

        if (kt + GEMM_STAGES - 1 < nt) {
            const int s = (kt + GEMM_STAGES - 1) & (GEMM_STAGES - 1);
            const uint32_t* a = Ag + (size_t)(kt + GEMM_STAGES - 1) * 16;
            const uint32_t* b = Bg + (size_t)(kt + GEMM_STAGES - 1) * 16;
            CP16(sA0 + s * STG_B, a); CP16(sA0 + s * STG_B + 16, a + 4);
            CP16(sB0 + s * STG_B, b); CP16(sB0 + s * STG_B + 16, b + 4);
        }
        asm volatile("cp.async.commit_group;");
    }

#pragma unroll
    for (int mi = 0; mi < 4; mi++) {
#pragma unroll
        for (int ni = 0; ni < 4; ni++) {
            int row0 = bm + wm + mi * 16 + g;
            int col  = bn + wn + ni * 8 + 2 * t;
            *(float2*)(C + (size_t)row0 * ldc + col) = make_float2(acc[mi][ni][0], acc[mi][ni][1]);
            *(float2*)(C + (size_t)(row0 + 8) * ldc + col) = make_float2(acc[mi][ni][2], acc[mi][ni][3]);
        }
    }
}

// ---------------- pack [Wq|Wk|Wv|Wg] TRANSPOSED (n-major) tf32 ----------------
__global__ void pack_w_kernel(const float* __restrict__ Wq, const float* __restrict__ Wk,
                              const float* __restrict__ Wv, const float* __restrict__ Wg)
{
    int idx = blockIdx.x * blockDim.x + threadIdx.x;
    if (idx >= cNP * cD) return;
    int n = idx / cD, k = idx % cD;
    float v;
    if (n < cKD)                 v = Wq[k * cKD + n];
    else if (n < 2 * cKD)        v = Wk[k * cKD + (n - cKD)];
    else if (n < 2 * cKD + cVD)  v = Wv[k * cVD + (n - 2 * cKD)];
    else                         v = Wg[k * cVD + (n - 2 * cKD - cVD)];
    g_Wcat[idx] = f2tf32(v);
}

__global__ void pack_wo_kernel(const float* __restrict__ Wo)
{
    int idx = blockIdx.x * blockDim.x + threadIdx.x;
    if (idx >= cD * cVD) return;
    int n = idx / cVD, k = idx % cVD;
    g_WoT[idx] = f2tf32(Wo[k * cD + n]);
}

__global__ void convert_u_kernel(const float4* __restrict__ u4)
{
    int idx = blockIdx.x * blockDim.x + threadIdx.x;
    if (idx >= cM * cD / 4) return;
    float4 v = u4[idx];
    uint4 r;
    r.x = f2tf32(v.x); r.y = f2tf32(v.y); r.z = f2tf32(v.z); r.w = f2tf32(v.w);
    ((uint4*)g_uT)[idx] = r;
}

// ---------------- gk / beta projections: warp per token, W in smem ----------------
__global__ void proj_gates_kernel(const float* __restrict__ u, const float* __restrict__ Wgk,
                                  const float* __restrict__ Wb, const float* __restrict__ b_b,
                                  const float* __restrict__ A_log, const float* __restrict__ dt_bias)
{
    extern __shared__ float sW[];   // [1024][16]
    const int tid = threadIdx.x;
    const int wid = tid >> 5;
    const int lane = tid & 31;

    for (int idx = tid; idx < cD * 16; idx += 256) {
        int i = idx >> 4, c = idx & 15;
        sW[idx] = (c < 8) ? Wgk[i * cH + c] : Wb[i * cH + (c - 8)];
    }
    __syncthreads();

    int m = blockIdx.x * 8 + wid;
    const float* ur = u + (size_t)m * cD;
    float s[16];
#pragma unroll
    for (int c = 0; c < 16; c++) s[c] = 0.f;
    for (int j = 0; j < 32; j++) {
        int i = lane + 32 * j;
        float uv = __ldg(ur + i);
        const float* wr = sW + i * 16;
#pragma unroll
        for (int c = 0; c < 16; c++) s[c] += uv * wr[c];
    }
#pragma unroll
    for (int c = 0; c < 16; c++) {
#pragma unroll
        for (int o = 16; o; o >>= 1) s[c] += __shfl_xor_sync(0xffffffffu, s[c], o);
    }
    if (lane < 8) {
        int h = lane;
        float x  = s[h] + dt_bias[h];
        float sp = (x > 20.f) ? x : log1pf(expf(x));
        float gkv = -expf(A_log[h]) * sp;
        int b = m / cL, l = m % cL;
        g_gk[((size_t)(b * cH + h)) * cL + l] = gkv;
    } else {
        int h = lane - 8;
        float bv = 1.f / (1.f + expf(-(s[8 + h] + b_b[h])));
        int b = m / cL, l = m % cL;
        g_bt[((size_t)(b * cH + h)) * cL + l] = bv;
    }
}

// ---------------- fused conv + SiLU + L2norm for q,k; writes head layout ----------------
__global__ void conv_qk_norm_kernel(const float* __restrict__ wq, const float* __restrict__ wk)
{
    int gw = (blockIdx.x * blockDim.x + threadIdx.x) >> 5;
    int lane = threadIdx.x & 31;
    if (gw >= cM * cH) return;
    int m = gw / cH, h = gw % cH;
    int b = m / cL, l = m % cL;
    const size_t rowbase = (size_t)(m - l) * cNP;

    float qv[3], kv[3];
    float ssq = 0.f, ssk = 0.f;
#pragma unroll
    for (int r = 0; r < 3; r++) {
        int c = h * cDK + lane + 32 * r;
        float aq = 0.f, ak = 0.f;
#pragma unroll
        for (int j = 0; j < 4; j++) {
            int ll = l - 3 + j;
            if (ll >= 0) {
                const float* rowp = g_proj + rowbase + (size_t)ll * cNP;
                aq += rowp[c]       * wq[c * 4 + j];
                ak += rowp[cKD + c] * wk[c * 4 + j];
            }
        }
        aq = aq / (1.f + expf(-aq));
        ak = ak / (1.f + expf(-ak));
        qv[r] = aq; kv[r] = ak;
        ssq += aq * aq; ssk += ak * ak;
    }
#pragma unroll
    for (int o = 16; o; o >>= 1) {
        ssq += __shfl_xor_sync(0xffffffffu, ssq, o);
        ssk += __shfl_xor_sync(0xffffffffu, ssk, o);
    }
    float iq = 1.f / fmaxf(sqrtf(ssq), 1e-12f);
    float ik = 1.f / fmaxf(sqrtf(ssk), 1e-12f);
    float* dq = g_qn + ((size_t)(b * cH + h) * cL + l) * cDK;
    float* dk = g_kn + ((size_t)(b * cH + h) * cL + l) * cDK;
#pragma unroll
    for (int r = 0; r < 3; r++) {
        dq[lane + 32 * r] = qv[r] * iq;
        dk[lane + 32 * r] = kv[r] * ik;
    }
}

// ---------------- conv + SiLU for v; writes head layout directly ----------------
__global__ void conv_v_kernel(const float* __restrict__ wv)
{
    int idx = blockIdx.x * blockDim.x + threadIdx.x;
    if (idx >= cM * cVD) return;
    int c = idx % cVD;
    int m = idx / cVD;
    int l = m % cL, b = m / cL;
    float acc = 0.f;
#pragma unroll
    for (int j = 0; j < 4; j++) {
        int ll = l - 3 + j;
        if (ll >= 0) acc += g_proj[(size_t)(m - l + ll) * cNP + 2 * cKD + c] * wv[c * 4 + j];
    }
    int h = c / cDV, d = c % cDV;
    g_vh[((size_t)(b * cH + h) * cL + l) * cDV + d] = acc / (1.f + expf(-acc));
}

// ---------------- per-chunk precompute (sk padded to stride 100) ----------------
constexpr int cSKS = 100;
constexpr int CP_SMEM_FLOATS = 6144 + 64 * cSKS + 6144 + 4096 + 4096 + 12288 + 64 + 64;
constexpr int CP_THREADS = 320;
__global__ void chunk_pre_kernel()
{
    extern __shared__ float sm[];
    float* sq   = sm;                    // 64 x 96
    float* sk   = sq + 6144;             // 64 x 100 (padded)
    float* skb  = sk + 64 * cSKS;        // 64 x 96
    float* sKK  = skb + 6144;            // 64 x 64
    float* sM   = sKK + 4096;            // 64 x 64
    float* sv   = sM + 4096;             // 64 x 192
    float* sdec = sv + 12288;
    float* sbet = sdec + 64;

    const int tid = threadIdx.x;
    const int cid = blockIdx.x;
    const int bh = cid / cNC;
    const int n  = cid % cNC;
    const size_t cbg  = (size_t)bh * cL + n * cCS;
    const size_t cb96  = cbg * cDK;
    const size_t cb192 = cbg * cDV;
    const float scale = rsqrtf((float)cDK);

    for (int i4 = tid; i4 < 1536; i4 += CP_THREADS) {
        ((float4*)sq)[i4] = ((const float4*)(g_qn + cb96))[i4];
        int c = i4 / 24, d4 = i4 % 24;
        ((float4*)sk)[c * (cSKS / 4) + d4] = ((const float4*)(g_kn + cb96))[i4];
    }
    if (tid < 64) sbet[tid] = g_bt[cbg + tid];
    if (tid < 32) {
        float x0 = g_gk[cbg + tid], x1 = g_gk[cbg + 32 + tid];
#pragma unroll
        for (int o = 1; o < 32; o <<= 1) {
            float y = __shfl_up_sync(0xffffffffu, x0, o);
            if (tid >= o) x0 += y;
        }
        float t0 = __shfl_sync(0xffffffffu, x0, 31);
#pragma unroll
        for (int o = 1; o < 32; o <<= 1) {
            float y = __shfl_up_sync(0xffffffffu, x1, o);
            if (tid >= o) x1 += y;
        }
        sdec[tid] = x0;
        sdec[32 + tid] = x1 + t0;
    }
    __syncthreads();
    const float dl = sdec[63];

    for (int i = tid; i < 6144; i += CP_THREADS) {
        int c = i / cDK, d = i - c * cDK;
        skb[i] = sk[c * cSKS + d] * sbet[c];
    }
    for (int i = tid; i < 12288; i += CP_THREADS) sv[i]  = g_vh[cb192 + i] * sbet[i / cDV];

    for (int i = tid; i < 6144; i += CP_THREADS) {
        int c = i / cDK, d = i - c * cDK;
        g_qn[cb96 + i] = sq[i] * scale * expf(sdec[c]);
        g_kn[cb96 + i] = sk[c * cSKS + d] * expf(dl - sdec[c]);
    }
    __syncthreads();

    for (int idx = tid; idx < 4096; idx += CP_THREADS) {
        int i = idx >> 6, j = idx & 63;
        float s = 0.f;
        const float4* a4 = (const float4*)(skb + i * cDK);
        const float4* b4 = (const float4*)(sk + j * cSKS);
#pragma unroll 6
        for (int d = 0; d < cDK / 4; d++) {
            float4 a = a4[d], b = b4[d];
            s += a.x * b.x + a.y * b.y + a.z * b.z + a.w * b.w;
        }
        sKK[idx] = s;
    }
    for (int idx = tid; idx < 4096; idx += CP_THREADS) {
        int i = idx >> 6, j = idx & 63;
        float a = 0.f;
        if (i >= j) {
            float s = 0.f;
            const float4* a4 = (const float4*)(sq + i * cDK);
            const float4* b4 = (const float4*)(sk + j * cSKS);
#pragma unroll 6
            for (int d = 0; d < cDK / 4; d++) {
                float4 x = a4[d], y = b4[d];
                s += x.x * y.x + x.y * y.y + x.z * y.z + x.w * y.w;
            }
            a = s * scale * expf(sdec[i] - sdec[j]);
        }
        g_at[(size_t)cid * 4096 + idx] = a;
    }
    for (int idx = tid; idx < 4096; idx += CP_THREADS) {
        int i = idx >> 6, j = idx & 63;
        sM[idx] = (i > j) ? sKK[idx] * expf(sdec[i] - sdec[j]) : 0.f;
    }
    __syncthreads();

    for (int i = 1; i < 64; i++) {
        if (tid < 192) {
            float s = 0.f;
            const float* mrow = sM + i * 64;
            int j = 0;
            for (; j + 4 <= i; j += 4) {
                float4 m4 = *(const float4*)(mrow + j);
                s += m4.x * sv[(j + 0) * 192 + tid] + m4.y * sv[(j + 1) * 192 + tid]
                   + m4.z * sv[(j + 2) * 192 + tid] + m4.w * sv[(j + 3) * 192 + tid];
            }
            for (; j < i; j++) s += mrow[j] * sv[j * 192 + tid];
            sv[i * 192 + tid] -= s;
        } else if (tid < 288) {
            int c = tid - 192;
            float s = 0.f;
            const float* krow = sKK + i * 64;
            int j = 0;
            for (; j + 4 <= i; j += 4) {
                float4 m4 = *(const float4*)(krow + j);
                s += m4.x * skb[(j + 0) * 96 + c] + m4.y * skb[(j + 1) * 96 + c]
                   + m4.z * skb[(j + 2) * 96 + c] + m4.w * skb[(j + 3) * 96 + c];
            }
            for (; j < i; j++) s += krow[j] * skb[j * 96 + c];
            skb[i * 96 + c] -= s;
        }
        __syncthreads();
    }

    for (int i = tid; i < 12288; i += CP_THREADS) g_vh[cb192 + i] = sv[i];
    for (int i = tid; i < 6144; i += CP_THREADS) {
        int c = i / cDK;
        g_kce[cb96 + i] = skb[i] * expf(sdec[c]);
    }
    if (tid == 0) g_edl[cid] = expf(dl);
}

// ---------------- sequential scan over chunks ----------------
constexpr int SC_SMEM_FLOATS = 3 * 6144 + 4096 + 2048 + 2048 + 3072;
constexpr int SC_THREADS = 512;
__global__ void scan_kernel()
{
    extern __shared__ float sm[];
    float* sqe  = sm;
    float* skce = sqe + 6144;
    float* skd  = skce + 6144;
    float* sat  = skd + 6144;
    float* su   = sat + 4096;
    float* svn  = su + 2048;
    float* S    = svn + 2048;   // 96 x 32

    const int tid = threadIdx.x;
    const int bh = blockIdx.y;
    const int e0 = blockIdx.x * 32;
    const int e  = tid & 31;
    const int w  = tid >> 5;
    const int c0 = w * 4;
    const int d0 = w * 6;

    for (int i = tid; i < 3072; i += SC_THREADS) S[i] = 0.f;

    for (int n = 0; n < cNC; n++) {
        const size_t cbg = (size_t)bh * cL + n * cCS;
        const size_t cb96 = cbg * cDK;
        const size_t cb192 = cbg * cDV;
        __syncthreads();
        for (int i = tid; i < 1536; i += SC_THREADS) {
            ((float4*)sqe)[i]  = ((const float4*)(g_qn + cb96))[i];
            ((float4*)skce)[i] = ((const float4*)(g_kce + cb96))[i];
            ((float4*)skd)[i]  = ((const float4*)(g_kn + cb96))[i];
        }
        for (int i = tid; i < 1024; i += SC_THREADS)
            ((float4*)sat)[i] = ((const float4*)(g_at + (size_t)(bh * cNC + n) * 4096))[i];
        for (int i = tid; i < 512; i += SC_THREADS) {
            int c = i >> 3, ee = (i & 7) * 4;
            *(float4*)&su[c * 32 + ee] =
                *(const float4*)&g_vh[cb192 + (size_t)c * cDV + e0 + ee];
        }
        __syncthreads();

        float accv[4], acco[4];
#pragma unroll
        for (int i = 0; i < 4; i++) { accv[i] = 0.f; acco[i] = 0.f; }
        for (int j = 0; j < cDK; j += 4) {
            float s0 = S[(j + 0) * 32 + e];
            float s1 = S[(j + 1) * 32 + e];
            float s2 = S[(j + 2) * 32 + e];
            float s3 = S[(j + 3) * 32 + e];
#pragma unroll
            for (int i = 0; i < 4; i++) {
                float4 kv = *(const float4*)&skce[(c0 + i) * cDK + j];
                float4 qv = *(const float4*)&sqe[(c0 + i) * cDK + j];
                accv[i] += kv.x * s0 + kv.y * s1 + kv.z * s2 + kv.w * s3;
                acco[i] += qv.x * s0 + qv.y * s1 + qv.z * s2 + qv.w * s3;
            }
        }
#pragma unroll
        for (int i = 0; i < 4; i++) svn[(c0 + i) * 32 + e] = su[(c0 + i) * 32 + e] - accv[i];
        __syncthreads();

        for (int j = 0; j < 64; j += 4) {
            float v0 = svn[(j + 0) * 32 + e];
            float v1 = svn[(j + 1) * 32 + e];
            float v2 = svn[(j + 2) * 32 + e];
            float v3 = svn[(j + 3) * 32 + e];
#pragma unroll
            for (int i = 0; i < 4; i++) {
                float4 av = *(const float4*)&sat[(c0 + i) * 64 + j];
                acco[i] += av.x * v0 + av.y * v1 + av.z * v2 + av.w * v3;
            }
        }
#pragma unroll
        for (int i = 0; i < 4; i++)
            g_o[cb192 + (size_t)(c0 + i) * cDV + e0 + e] = acco[i];

        const float el = g_edl[bh * cNC + n];
        float accS[6];
#pragma unroll
        for (int ii = 0; ii < 6; ii++) accS[ii] = 0.f;
        for (int c = 0; c < 64; c++) {
            float v = svn[c * 32 + e];
            const float* kr = skd + c * cDK + d0;
            float2 k0 = *(const float2*)(kr);
            float2 k1 = *(const float2*)(kr + 2);
            float2 k2 = *(const float2*)(kr + 4);
            accS[0] += k0.x * v; accS[1] += k0.y * v;
            accS[2] += k1.x * v; accS[3] += k1.y * v;
            accS[4] += k2.x * v; accS[5] += k2.y * v;
        }
#pragma unroll
        for (int ii = 0; ii < 6; ii++) {
            int idx = (d0 + ii) * 32 + e;
            S[idx] = S[idx] * el + accS[ii];
        }
    }
}

// ---------------- gated RMS norm + transpose back (writes tf32 bits) ----------------
__global__ void gate_norm_kernel(const float* __restrict__ norm_w)
{
    int gw = (blockIdx.x * blockDim.x + threadIdx.x) >> 5;
    int lane = threadIdx.x & 31;
    if (gw >= cM * cH) return;
    int m = gw / cH, h = gw % cH;
    int b = m / cL, l = m % cL;
    const float* orow = g_o + ((size_t)(b * cH + h) * cL + l) * cDV;
    float vals[6];
    float ss = 0.f;
#pragma unroll
    for (int k = 0; k < 6; k++) {
        float v = orow[lane + 32 * k];
        vals[k] = v;
        ss += v * v;
    }
#pragma unroll
    for (int o = 16; o; o >>= 1) ss += __shfl_xor_sync(0xffffffffu, ss, o);
    float r = 1.f / sqrtf(ss / (float)cDV + 1e-5f);
#pragma unroll
    for (int k = 0; k < 6; k++) {
        int d = lane + 32 * k;
        float gg = g_proj[(size_t)m * cNP + 2 * cKD + cVD + h * cDV + d];
        float sg = gg / (1.f + expf(-gg));
        g_on[(size_t)m * cVD + h * cDV + d] = f2tf32(vals[k] * r * norm_w[d] * sg);
    }
}

// ---------------- host launch ----------------
template <typename T>
static T* sym(const void* symbol)
{
    void* p = nullptr;
    cudaGetSymbolAddress(&p, symbol);
    return (T*)p;
}

extern "C" void kernel_launch(void* const* d_in, const int* in_sizes, int n_in,
                              void* d_out, int out_size)
{
    const float* u       = (const float*)d_in[0];
    const float* Wq      = (const float*)d_in[1];
    const float* Wk      = (const float*)d_in[2];
    const float* Wv      = (const float*)d_in[3];
    const float* Wg      = (const float*)d_in[4];
    const float* Wo      = (const float*)d_in[5];
    const float* Wgk     = (const float*)d_in[6];
    const float* Wb      = (const float*)d_in[7];
    const float* b_b     = (const float*)d_in[8];
    const float* A_log   = (const float*)d_in[9];
    const float* dt_bias = (const float*)d_in[10];
    const float* conv_q  = (const float*)d_in[11];
    const float* conv_k  = (const float*)d_in[12];
    const float* conv_v  = (const float*)d_in[13];
    const float* norm_w  = (const float*)d_in[14];
    float* out = (float*)d_out;

    uint32_t* Wcat = sym<uint32_t>(g_Wcat);
    uint32_t* WoT  = sym<uint32_t>(g_WoT);
    uint32_t* uT   = sym<uint32_t>(g_uT);
    uint32_t* on   = sym<uint32_t>(g_on);
    float* proj = sym<float>(g_proj);

    cudaFuncSetAttribute(gemm_tf32_kernel, cudaFuncAttributeMaxDynamicSharedMemorySize, GEMM_SMEM);
    cudaFuncSetAttribute(chunk_pre_kernel, cudaFuncAttributeMaxDynamicSharedMemorySize,
                         CP_SMEM_FLOATS * (int)sizeof(float));
    cudaFuncSetAttribute(scan_kernel, cudaFuncAttributeMaxDynamicSharedMemorySize,
                         SC_SMEM_FLOATS * (int)sizeof(float));
    cudaFuncSetAttribute(proj_gates_kernel, cudaFuncAttributeMaxDynamicSharedMemorySize, 65536);

    // pack/convert (B operands transposed to n-major)
    pack_w_kernel<<<(cNP * cD + 255) / 256, 256>>>(Wq, Wk, Wv, Wg);
    convert_u_kernel<<<(cM * cD / 4 + 255) / 256, 256>>>((const float4*)u);
    pack_wo_kernel<<<(cD * cVD + 255) / 256, 256>>>(Wo);

    // fused projection GEMM (q|k|v|g)
    gemm_tf32_kernel<<<dim3(cNP / 128, cM / 128), 256, GEMM_SMEM>>>(
        uT, cD, Wcat, cD, proj, cNP, cM, cNP, cD);

    // gates
    proj_gates_kernel<<<cM / 8, 256, 65536>>>(u, Wgk, Wb, b_b, A_log, dt_bias);

    // fused conv+silu(+l2norm) -> head layouts
    conv_qk_norm_kernel<<<(cM * cH * 32 + 255) / 256, 256>>>(conv_q, conv_k);
    conv_v_kernel<<<(cM * cVD + 255) / 256, 256>>>(conv_v);

    // delta-rule chunk precompute + scan
    chunk_pre_kernel<<<cBH * cNC, CP_THREADS, CP_SMEM_FLOATS * sizeof(float)>>>();
    scan_kernel<<<dim3(6, cBH), SC_THREADS, SC_SMEM_FLOATS * sizeof(float)>>>();

    // gated rms norm + output projection
    gate_norm_kernel<<<(cM * cH * 32 + 255) / 256, 256>>>(norm_w);
    gemm_tf32_kernel<<<dim3(cD / 128, cM / 128), 256, GEMM_SMEM>>>(
        on, cVD, WoT, cVD, out, cD, cM, cD, cVD);
}